// round 12
// baseline (speedup 1.0000x reference)
#include <cuda_runtime.h>
#include <math_constants.h>

#define NN  1024
#define VV  32000
#define BB  16
#define TT  128
#define GG  128            // CTAs in forward kernel (all co-resident)
#define RR  (NN/GG)        // 8 rows of E_T per CTA
#define TPB 256

typedef unsigned long long ull;

// ---------------- device scratch (static; no runtime alloc) ----------------
__device__ unsigned short d_ETh[NN*NN];       // bf16 exp(log_T' - rowmax), 2 MB
__device__ float          d_rowmax[NN];
__device__ float          d_rowlse[NN];
__device__ float          d_collse[NN];
__device__ float          d_piadj[NN];        // log_pi - rowmax
__device__ float          d_emitg[TT*NN*BB];  // emit - rowlse + rowmax, [t][m][b]
__device__ unsigned short d_eag[2][BB*NN];    // bf16 exp(alpha - shift), ping-pong
__device__ float          d_easum[TT*BB];     // sum_n ea per (t,b)
__device__ float          d_shift[TT*BB];     // shift used per (t,b)
__device__ unsigned       d_barcnt;           // grid barrier counter

// ---------------- helpers ----------------
__device__ __forceinline__ ull ffma2(ull a, ull b, ull c) {
    ull d;
    asm("fma.rn.f32x2 %0, %1, %2, %3;" : "=l"(d) : "l"(a), "l"(b), "l"(c));
    return d;
}
__device__ __forceinline__ ull bf2f32x2(unsigned u) {
    unsigned lo = u << 16, hi = u & 0xffff0000u;
    ull p;
    asm("mov.b64 %0, {%1,%2};" : "=l"(p) : "r"(lo), "r"(hi));
    return p;
}
__device__ __forceinline__ void cp_async16(unsigned dst_smem, const void* src) {
    asm volatile("cp.async.cg.shared.global [%0], [%1], 16;"
                 :: "r"(dst_smem), "l"(src));
}
__device__ __forceinline__ unsigned bf16x2pack(float lo, float hi) {
    unsigned r;
    asm("cvt.rn.bf16x2.f32 %0, %1, %2;" : "=r"(r) : "f"(hi), "f"(lo));
    return r;
}

// ---------------- prep kernel 1: rowlse (0..1023) + collse (1024..1055) ----
__global__ void k_pre1(const float* __restrict__ emis,
                       const float* __restrict__ trans) {
    if (blockIdx.x < NN) {
        int n = blockIdx.x;
        const float* row = emis + (size_t)n * VV;
        float mx = -CUDART_INF_F, s = 0.f;
        for (int i = threadIdx.x; i < VV; i += TPB) {
            float v = row[i];
            if (v > mx) { s = s * __expf(mx - v) + 1.f; mx = v; }
            else        { s += __expf(v - mx); }
        }
        __shared__ float smx[TPB], ss[TPB];
        smx[threadIdx.x] = mx; ss[threadIdx.x] = s;
        __syncthreads();
        for (int off = TPB / 2; off; off >>= 1) {
            if (threadIdx.x < off) {
                float m1 = smx[threadIdx.x], s1 = ss[threadIdx.x];
                float m2 = smx[threadIdx.x + off], s2 = ss[threadIdx.x + off];
                float m = fmaxf(m1, m2);
                ss[threadIdx.x]  = s1 * __expf(m1 - m) + s2 * __expf(m2 - m);
                smx[threadIdx.x] = m;
            }
            __syncthreads();
        }
        if (threadIdx.x == 0) d_rowlse[n] = smx[0] + __logf(ss[0]);
    } else {
        int tx = threadIdx.x & 31, ty = threadIdx.x >> 5;   // 32 x 8
        int col = (blockIdx.x - NN) * 32 + tx;
        float mx = -CUDART_INF_F, s = 0.f;
        for (int m = ty; m < NN; m += 8) {
            float v = trans[m * NN + col];
            if (v > mx) { s = s * __expf(mx - v) + 1.f; mx = v; }
            else        { s += __expf(v - mx); }
        }
        __shared__ float cmx[8][32], cs[8][32];
        cmx[ty][tx] = mx; cs[ty][tx] = s;
        __syncthreads();
        if (ty == 0) {
            float m1 = mx, s1 = s;
            for (int j = 1; j < 8; j++) {
                float m2 = cmx[j][tx], s2 = cs[j][tx];
                float m = fmaxf(m1, m2);
                s1 = s1 * __expf(m1 - m) + s2 * __expf(m2 - m);
                m1 = m;
            }
            d_collse[col] = m1 + __logf(s1);
        }
    }
}

// ---------------- prep kernel 2: rowmax + bf16 E_T ----------------
__global__ void k_prepT(const float* __restrict__ trans) {
    int m = blockIdx.x;
    const float* rowp = trans + (size_t)m * NN;
    float mx = -CUDART_INF_F;
    for (int n = threadIdx.x; n < NN; n += TPB)
        mx = fmaxf(mx, rowp[n] - d_collse[n]);
    __shared__ float smx[TPB];
    smx[threadIdx.x] = mx; __syncthreads();
    for (int off = TPB / 2; off; off >>= 1) {
        if (threadIdx.x < off)
            smx[threadIdx.x] = fmaxf(smx[threadIdx.x], smx[threadIdx.x + off]);
        __syncthreads();
    }
    float rm = smx[0];
    if (threadIdx.x == 0) d_rowmax[m] = rm;
    for (int n = threadIdx.x; n < NN; n += TPB) {
        float e = __expf(rowp[n] - d_collse[n] - rm);
        unsigned r;
        asm("cvt.rn.bf16x2.f32 %0, %1, %2;" : "=r"(r) : "f"(0.f), "f"(e));
        d_ETh[m * NN + n] = (unsigned short)(r & 0xffffu);
    }
}

// ---------------- prep kernel 3: gather (0..127) + init (128..143) ---------
__global__ void k_pre3(const float* __restrict__ emis,
                       const int* __restrict__ x,
                       const float* __restrict__ pri) {
    if (blockIdx.x < TT) {
        int t = blockIdx.x;
        __shared__ int tok[BB];
        if (threadIdx.x < BB) tok[threadIdx.x] = x[threadIdx.x * TT + t];
        __syncthreads();
        float* dst = d_emitg + (size_t)t * NN * BB;
        for (int i = threadIdx.x; i < NN * BB; i += TPB) {
            int m = i >> 4, b = i & 15;
            dst[i] = __ldg(&emis[(size_t)m * VV + tok[b]])
                     - d_rowlse[m] + d_rowmax[m];
        }
    } else {
        int j = blockIdx.x - TT;   // 0..15
        if (threadIdx.x < 128) d_easum[j * 128 + threadIdx.x] = 0.f;
        if (j == 0) {
            if (threadIdx.x == 0) d_barcnt = 0u;
            float mx = -CUDART_INF_F, s = 0.f;
            for (int i = threadIdx.x; i < NN; i += TPB) {
                float v = pri[i];
                if (v > mx) { s = s * __expf(mx - v) + 1.f; mx = v; }
                else        { s += __expf(v - mx); }
            }
            __shared__ float smx[TPB], ss[TPB];
            smx[threadIdx.x] = mx; ss[threadIdx.x] = s;
            __syncthreads();
            for (int off = TPB / 2; off; off >>= 1) {
                if (threadIdx.x < off) {
                    float m1 = smx[threadIdx.x], s1 = ss[threadIdx.x];
                    float m2 = smx[threadIdx.x + off], s2 = ss[threadIdx.x + off];
                    float m = fmaxf(m1, m2);
                    ss[threadIdx.x]  = s1 * __expf(m1 - m) + s2 * __expf(m2 - m);
                    smx[threadIdx.x] = m;
                }
                __syncthreads();
            }
            __shared__ float lp;
            if (threadIdx.x == 0) lp = smx[0] + __logf(ss[0]);
            __syncthreads();
            for (int m = threadIdx.x; m < NN; m += TPB)
                d_piadj[m] = pri[m] - lp - d_rowmax[m];
        }
    }
}

// ---------------- persistent forward (R9 skeleton, E in regs) ---------------
// smem: ea bf16 32KB | part [2][128][8] floats 8KB | eat 128 floats
#define PART_OFF (BB*NN*2)
#define EAT_OFF  (PART_OFF + 2*128*8*4)
#define FWD_SMEM (EAT_OFF + 128*4)

__global__ void __launch_bounds__(TPB, 1)
k_forward(const int* __restrict__ len, float* __restrict__ out) {
    extern __shared__ char sh[];
    char*  ea_sh  = sh;                          // [BB][NN] bf16, 32KB
    float* part   = (float*)(sh + PART_OFF);     // [2][128][8]
    float* eat_sh = (float*)(sh + EAT_OFF);      // [128]
    __shared__ float sA[BB], sB[BB];
    __shared__ unsigned sdone;

    const int g = blockIdx.x, tid = threadIdx.x;
    const int w = tid >> 5, lane = tid & 31;
    const int nh = w >> 2;                 // n-half
    const int mt = w & 1, bt = (w >> 1) & 1;
    const int ltid = tid & 127;
    const unsigned ea_smem = (unsigned)__cvta_generic_to_shared(ea_sh);

    // load + pre-expand this warp's E_T tile into registers (once)
    ull Ef[2][4][4];
#pragma unroll
    for (int cc = 0; cc < 2; cc++) {
        int n0 = nh * 512 + cc * 256 + lane * 8;
#pragma unroll
        for (int j = 0; j < 4; j++) {
            uint4 ev = *(const uint4*)
                &d_ETh[(size_t)(g * RR + mt * 4 + j) * NN + n0];
            Ef[cc][j][0] = bf2f32x2(ev.x);
            Ef[cc][j][1] = bf2f32x2(ev.y);
            Ef[cc][j][2] = bf2f32x2(ev.z);
            Ef[cc][j][3] = bf2f32x2(ev.w);
        }
    }
    if (tid < BB) { sA[tid] = 0.f; sB[tid] = 0.f; }
    if (tid == 0) sdone = 0u;
    float lseP = 0.f, sPrev = 0.f;                   // tid<16 state
    __syncthreads();

    const int b_f = tid & 15, m_f = g * RR + (tid >> 4);

    for (int t = 0; t < TT; t++) {
        // prefetches: emit term + easum(t-1)
        float em = 0.f, pa = 0.f, easumP = 0.f;
        if (tid < RR * BB) {
            em = __ldcg(&d_emitg[((size_t)t * NN + m_f) * BB + b_f]);
            if (t == 0) pa = __ldcg(&d_piadj[m_f]);
        }
        if (tid < BB && t >= 1)
            easumP = __ldcg(&d_easum[(t - 1) * BB + tid]);

        // -------- matvec: 2 chunks per n-half, per-half barrier pipeline ----
        if (t > 0) {
            ull acc[4][8];
#pragma unroll
            for (int j = 0; j < 4; j++)
#pragma unroll
                for (int k = 0; k < 8; k++) acc[j][k] = 0ull;
#pragma unroll
            for (int cc = 0; cc < 2; cc++) {
                if (cc == 0) asm volatile("cp.async.wait_group 1;");
                else         asm volatile("cp.async.wait_group 0;");
                asm volatile("bar.sync %0, 128;" :: "r"(2 + nh));
                int n0 = nh * 512 + cc * 256 + lane * 8;   // 8 bf16 per lane
#pragma unroll
                for (int k = 0; k < 8; k++) {
                    uint4 av = *(const uint4*)(ea_sh + ((bt * 8 + k) * NN + n0) * 2);
                    ull a0 = bf2f32x2(av.x), a1 = bf2f32x2(av.y);
                    ull a2 = bf2f32x2(av.z), a3 = bf2f32x2(av.w);
#pragma unroll
                    for (int j = 0; j < 4; j++) {
                        acc[j][k] = ffma2(Ef[cc][j][0], a0, acc[j][k]);
                        acc[j][k] = ffma2(Ef[cc][j][1], a1, acc[j][k]);
                        acc[j][k] = ffma2(Ef[cc][j][2], a2, acc[j][k]);
                        acc[j][k] = ffma2(Ef[cc][j][3], a3, acc[j][k]);
                    }
                }
            }
            // 2-level reduce; lanes 0-7 store partials to smem
#pragma unroll
            for (int j = 0; j < 4; j++)
#pragma unroll
                for (int k = 0; k < 8; k++) {
                    float2 f = *(float2*)&acc[j][k];
                    float r = f.x + f.y;
                    r += __shfl_xor_sync(0xffffffffu, r, 16);
                    r += __shfl_xor_sync(0xffffffffu, r, 8);
                    if (lane < 8)
                        part[(nh * 128 + (mt * 4 + j) * 16 + bt * 8 + k) * 8
                             + lane] = r;
                }
        }

        // -------- shift(t) from lse(t-1) (prefetched easum) --------
        if (tid < BB) {
            float sh_t;
            if (t == 0) sh_t = 0.f;
            else {
                float lse = sPrev + __logf(easumP);          // lse(t-1)
                float d = (t == 1) ? 0.f
                                   : fminf(20.f, fmaxf(-40.f, lse - lseP));
                sh_t = lse + d;
                lseP = lse;
            }
            sA[tid] = sPrev;
            sB[tid] = sh_t;
            sPrev = sh_t;
            if (g == 0) d_shift[t * BB + tid] = sh_t;
        }
        __syncthreads();

        // -------- finalize: sum partials -> alpha -> ea (shifted) --------
        if (tid < RR * BB) {
            float A;
            if (t == 0) A = em + pa;
            else {
                const float4* p0 = (const float4*)(part + tid * 8);
                const float4* p1 = (const float4*)(part + 1024 + tid * 8);
                float4 x0 = p0[0], x1 = p0[1], y0 = p1[0], y1 = p1[1];
                float ssum = ((x0.x + x0.y) + (x0.z + x0.w))
                           + ((x1.x + x1.y) + (x1.z + x1.w))
                           + ((y0.x + y0.y) + (y0.z + y0.w))
                           + ((y1.x + y1.y) + (y1.z + y1.w));
                A = em + sA[b_f] + __logf(ssum);
            }
            eat_sh[tid] = __expf(A - sB[b_f]);
        }
        __syncthreads();

        // pack bf16 pairs -> d_eag[t&1]
        if (tid < 64) {
            int b = tid >> 2, q = tid & 3;
            float e0 = eat_sh[(2 * q) * BB + b];
            float e1 = eat_sh[(2 * q + 1) * BB + b];
            unsigned* dst = (unsigned*)&d_eag[t & 1][b * NN + g * RR + 2 * q];
            *dst = bf16x2pack(e0, e1);
        }
        // per-batch partial sums -> global
        if (tid < BB) {
            float sm = eat_sh[tid];
#pragma unroll
            for (int ml = 1; ml < RR; ml++) sm += eat_sh[ml * BB + tid];
            atomicAdd(&d_easum[t * BB + tid], sm);
        }

        // -------- grid barrier: release + 4 staggered pollers --------
        {
            unsigned tgt = (unsigned)(t + 1) * GG;
            __syncthreads();
            if (tid == 0)
                asm volatile("red.release.gpu.add.u32 [%0], 1;"
                             :: "l"(&d_barcnt));
            if (tid < 128 && (tid & 31) == 0) {
                volatile unsigned* sd = &sdone;
                while (*sd != tgt) {
                    unsigned v;
                    asm volatile("ld.acquire.gpu.u32 %0, [%1];"
                                 : "=r"(v) : "l"(&d_barcnt));
                    if (v >= tgt) { *sd = tgt; break; }
                }
            }
            __syncthreads();
        }

        // -------- issue async reload of ea(t) for step t+1 (per half) ------
        if (t < TT - 1) {
            const char* src = (const char*)d_eag[t & 1];
#pragma unroll
            for (int cc = 0; cc < 2; cc++) {
#pragma unroll
                for (int k = 0; k < 4; k++) {
                    int idx = ltid + 128 * k;        // [0,512) 16B units
                    int b = idx >> 5, o = idx & 31;
                    unsigned off =
                        (unsigned)(b * (NN * 2) + nh * 1024 + cc * 512 + o * 16);
                    cp_async16(ea_smem + off, src + off);
                }
                asm volatile("cp.async.commit_group;");
            }
        }
    }

    // final output: out[b] = shift[len-1] + log(easum[len-1])
    if (g == 0 && tid < BB) {
        int tb = len[tid] - 1;
        tb = tb < 0 ? 0 : (tb > TT - 1 ? TT - 1 : tb);
        out[tid] = d_shift[tb * BB + tid] + __logf(__ldcg(&d_easum[tb * BB + tid]));
    }
}

// ---------------- launch: 4 kernels; forward is launch #4 ----------------
extern "C" void kernel_launch(void* const* d_in, const int* in_sizes, int n_in,
                              void* d_out, int out_size) {
    (void)in_sizes; (void)n_in; (void)out_size;
    const float* emis  = (const float*)d_in[0];  // (N, V)
    const float* trans = (const float*)d_in[1];  // (N, N)
    const float* pri   = (const float*)d_in[2];  // (N,)
    const int*   x     = (const int*)d_in[3];    // (B, T)
    const int*   len   = (const int*)d_in[4];    // (B,)
    float*       out   = (float*)d_out;          // (B, 1)

    cudaFuncSetAttribute(k_forward, cudaFuncAttributeMaxDynamicSharedMemorySize,
                         FWD_SMEM);

    k_pre1<<<NN + NN / 32, TPB>>>(emis, trans);   // rowlse + collse
    k_prepT<<<NN, TPB>>>(trans);                  // rowmax + bf16 E_T
    k_pre3<<<TT + 16, TPB>>>(emis, x, pri);       // gather + init
    k_forward<<<GG, TPB, FWD_SMEM>>>(len, out);   // launch #4
}